// round 6
// baseline (speedup 1.0000x reference)
#include <cuda_runtime.h>

// ConvSepKanCell: per-pixel dynamic KAN — float2 (2 pixels/thread), 2 outputs/thread.
// x: (2, 16, 128, 128) f32   w: (2, 3328, 128, 128) f32   out: (2, 16, 128, 128) f32
// Param layout along dim-1 of w (per pixel):
//   [0, 2816)      coef[i][o][m]  (16 x 16 x 11)
//   [2816, 3072)   uw[i][o]
//   [3072, 3328)   rw[i][o]
// y[o] = sum_i uw[i][o] * (sum_m coef[i][o][m]*B3_m(x_i)) + rw[i][o]*silu(x_i)

#define HW      16384
#define HW2     8192      // float2 elements per image plane
#define INC     16
#define OUTC    16
#define COEFM   11
#define SIZE_W  3328
#define I0      2816
#define I1      3072
#define OSPLIT  8         // outputs per thread = 2
#define TPB     64

__device__ __forceinline__ float2 ldcs2(const float2* p) { return __ldcs(p); }

__global__ __launch_bounds__(TPB, 16)
void kan_kernel(const float* __restrict__ x,
                const float* __restrict__ w,
                float* __restrict__ out)
{
    const int t     = blockIdx.x * TPB + threadIdx.x;   // 0..16383 (float2 slots)
    const int slice = blockIdx.y;                       // 0..7 -> outputs slice*2..+2
    const int b   = t >> 13;
    const int hw2 = t & (HW2 - 1);

    const float2* wp = (const float2*)(w + (size_t)b * SIZE_W * HW) + hw2;
    const float2* xp = (const float2*)(x + (size_t)b * INC * HW) + hw2;

    const float2* cp = wp + (size_t)(slice * 2 * COEFM) * HW2;
    const float2* up = wp + (size_t)(I0 + slice * 2) * HW2;
    const float2* rp = wp + (size_t)(I1 + slice * 2) * HW2;

    float y0a = 0.f, y0b = 0.f, y1a = 0.f, y1b = 0.f;

    for (int i = 0; i < INC; ++i) {
        const float2 xi = __ldg(xp);
        xp += HW2;

        // ---- Cox-de Boor, K=3, uniform knots grid[j] = 0.25j - 1.75 (exact fp32) ----
        float ba[14], bc[14];
        #pragma unroll
        for (int j = 0; j < 14; ++j) {
            const float gj = 0.25f * (float)j - 1.75f;
            ba[j] = (xi.x >= gj && xi.x < gj + 0.25f) ? 1.f : 0.f;
            bc[j] = (xi.y >= gj && xi.y < gj + 0.25f) ? 1.f : 0.f;
        }
        const float ta = fmaf(xi.x, 4.0f, 7.0f);
        const float tc = fmaf(xi.y, 4.0f, 7.0f);
        #pragma unroll
        for (int p = 1; p <= 3; ++p) {
            const float invp = 1.0f / (float)p;
            #pragma unroll
            for (int j = 0; j < 14 - p; ++j) {
                const float la = (ta - (float)j) * invp;
                const float ra = ((float)(j + p + 1) - ta) * invp;
                ba[j] = la * ba[j] + ra * ba[j + 1];
                const float lc = (tc - (float)j) * invp;
                const float rc = ((float)(j + p + 1) - tc) * invp;
                bc[j] = lc * bc[j] + rc * bc[j + 1];
            }
        }
        const float sxa = xi.x / (1.0f + __expf(-xi.x));
        const float sxb = xi.y / (1.0f + __expf(-xi.y));

        // ---- spline contraction for 2 outputs x 2 pixels ----
        float s0a = 0.f, s0b = 0.f, s1a = 0.f, s1b = 0.f;
        #pragma unroll
        for (int m = 0; m < COEFM; ++m) {
            const float2 c0 = ldcs2(cp + (0 * COEFM + m) * HW2);
            const float2 c1 = ldcs2(cp + (1 * COEFM + m) * HW2);
            s0a = fmaf(c0.x, ba[m], s0a);
            s0b = fmaf(c0.y, bc[m], s0b);
            s1a = fmaf(c1.x, ba[m], s1a);
            s1b = fmaf(c1.y, bc[m], s1b);
        }
        const float2 u0 = ldcs2(up + 0 * HW2);
        const float2 u1 = ldcs2(up + 1 * HW2);
        const float2 r0 = ldcs2(rp + 0 * HW2);
        const float2 r1 = ldcs2(rp + 1 * HW2);
        y0a += u0.x * s0a + r0.x * sxa;
        y0b += u0.y * s0b + r0.y * sxb;
        y1a += u1.x * s1a + r1.x * sxa;
        y1b += u1.y * s1b + r1.y * sxb;

        cp += (size_t)(OUTC * COEFM) * HW2;
        up += (size_t)OUTC * HW2;
        rp += (size_t)OUTC * HW2;
    }

    float2* op = (float2*)(out + (size_t)b * OUTC * HW) + (size_t)(slice * 2) * HW2 + hw2;
    op[0 * HW2] = make_float2(y0a, y0b);
    op[1 * HW2] = make_float2(y1a, y1b);
}

extern "C" void kernel_launch(void* const* d_in, const int* in_sizes, int n_in,
                              void* d_out, int out_size)
{
    const float* x = (const float*)d_in[0];
    const float* w = (const float*)d_in[1];
    float* out = (float*)d_out;

    dim3 grid(16384 / TPB, OSPLIT);   // (256, 8) = 2048 blocks of 64 threads
    kan_kernel<<<grid, TPB>>>(x, w, out);
}

// round 7
// speedup vs baseline: 1.1378x; 1.1378x over previous
#include <cuda_runtime.h>
#include <cstdint>

// ConvSepKanCell: per-pixel dynamic KAN — float2, 2 outputs/thread, L2-prefetch pipelined.
// x: (2, 16, 128, 128) f32   w: (2, 3328, 128, 128) f32   out: (2, 16, 128, 128) f32
// Param layout along dim-1 of w (per pixel):
//   [0, 2816)      coef[i][o][m]  (16 x 16 x 11)   planes (i*176 + o*11 + m)
//   [2816, 3072)   uw[i][o]
//   [3072, 3328)   rw[i][o]
// y[o] = sum_i uw[i][o] * (sum_m coef[i][o][m]*B3_m(x_i)) + rw[i][o]*silu(x_i)

#define HW      16384
#define HW2     8192                  // float2 per plane
#define PLANE_B 65536ull              // bytes per parameter plane
#define INC     16
#define OUTC    16
#define COEFM   11
#define SIZE_W  3328
#define I0      2816
#define I1      3072
#define OSPLIT  8
#define TPB     128

__device__ __forceinline__ float2 ldcs2(const float2* p) { return __ldcs(p); }
__device__ __forceinline__ void pf_l2(const char* p) {
    asm volatile("prefetch.global.L2 [%0];" :: "l"(p));
}

__global__ __launch_bounds__(TPB, 7)
void kan_kernel(const float* __restrict__ x,
                const float* __restrict__ w,
                float* __restrict__ out)
{
    const int t     = blockIdx.x * TPB + threadIdx.x;   // float2 slot
    const int slice = blockIdx.y;                       // 0..7
    const int b   = t >> 13;
    const int hw2 = t & (HW2 - 1);
    const int lane = threadIdx.x & 31;

    const float2* wp = (const float2*)(w + (size_t)b * SIZE_W * HW) + hw2;
    const float2* xp = (const float2*)(x + (size_t)b * INC * HW) + hw2;

    const float2* cp = wp + (size_t)(slice * 2 * COEFM) * HW2;
    const float2* up = wp + (size_t)(I0 + slice * 2) * HW2;
    const float2* rp = wp + (size_t)(I1 + slice * 2) * HW2;

    // ---------- lane-specialized L2 prefetch pointers (next iteration's lines) ----
    // One warp touches 26 planes x 256B = 52 lines per iteration.
    // pf1: lanes 0..31 -> coef planes 0..15 (rel. to cp), line = lane&1
    // pf2: lanes 0..11 -> coef planes 16..21 ; lanes 12..19 -> u0,u1,r0,r1 ; rest dup.
    const char* wbase = (const char*)(w + (size_t)b * SIZE_W * HW);
    const size_t warp_byte = (size_t)(hw2 & ~31) * 8 + (size_t)(lane & 1) * 128;

    const char* pf1 = wbase + (size_t)(slice * 2 * COEFM + (lane >> 1)) * PLANE_B + warp_byte;
    size_t pf2_plane;
    size_t pf2_stride;
    if (lane < 12) {                          // coef planes 16..21
        pf2_plane  = (size_t)(slice * 2 * COEFM + 16 + (lane >> 1));
        pf2_stride = (size_t)(OUTC * COEFM) * PLANE_B;      // 176 planes / iter
    } else {
        const int q = (lane < 20) ? (lane - 12) : 0;         // dup lanes 20..31
        const int prm = q >> 1;                              // 0..3: u0,u1,r0,r1
        pf2_plane  = (prm < 2) ? (size_t)(I0 + slice * 2 + prm)
                               : (size_t)(I1 + slice * 2 + (prm - 2));
        pf2_stride = (size_t)OUTC * PLANE_B;                 // 16 planes / iter
    }
    const char* pf2 = wbase + pf2_plane * PLANE_B +
                      (size_t)(hw2 & ~31) * 8 + (size_t)(((lane < 20 ? lane - 12 : 0) & 1)) * 128;
    const size_t pf1_stride = (size_t)(OUTC * COEFM) * PLANE_B;
    // advance to iteration 1 (iteration 0 is demand-loaded immediately)
    pf1 += pf1_stride;
    pf2 += pf2_stride;

    float y0a = 0.f, y0b = 0.f, y1a = 0.f, y1b = 0.f;

    for (int i = 0; i < INC; ++i) {
        // prefetch next iteration's 52 lines into L2 (2 instructions per warp)
        if (i < INC - 1) {
            pf_l2(pf1);
            pf_l2(pf2);
            pf1 += pf1_stride;
            pf2 += pf2_stride;
        }

        const float2 xi = __ldg(xp);
        xp += HW2;

        // ---- Cox-de Boor, K=3, uniform knots grid[j] = 0.25j - 1.75 (exact fp32) ----
        float ba[14], bc[14];
        #pragma unroll
        for (int j = 0; j < 14; ++j) {
            const float gj = 0.25f * (float)j - 1.75f;
            ba[j] = (xi.x >= gj && xi.x < gj + 0.25f) ? 1.f : 0.f;
            bc[j] = (xi.y >= gj && xi.y < gj + 0.25f) ? 1.f : 0.f;
        }
        const float ta = fmaf(xi.x, 4.0f, 7.0f);
        const float tc = fmaf(xi.y, 4.0f, 7.0f);
        #pragma unroll
        for (int p = 1; p <= 3; ++p) {
            const float invp = 1.0f / (float)p;
            #pragma unroll
            for (int j = 0; j < 14 - p; ++j) {
                const float la = (ta - (float)j) * invp;
                const float ra = ((float)(j + p + 1) - ta) * invp;
                ba[j] = la * ba[j] + ra * ba[j + 1];
                const float lc = (tc - (float)j) * invp;
                const float rc = ((float)(j + p + 1) - tc) * invp;
                bc[j] = lc * bc[j] + rc * bc[j + 1];
            }
        }
        const float sxa = xi.x / (1.0f + __expf(-xi.x));
        const float sxb = xi.y / (1.0f + __expf(-xi.y));

        // ---- spline contraction for 2 outputs x 2 pixels ----
        float s0a = 0.f, s0b = 0.f, s1a = 0.f, s1b = 0.f;
        #pragma unroll
        for (int m = 0; m < COEFM; ++m) {
            const float2 c0 = ldcs2(cp + (0 * COEFM + m) * HW2);
            const float2 c1 = ldcs2(cp + (1 * COEFM + m) * HW2);
            s0a = fmaf(c0.x, ba[m], s0a);
            s0b = fmaf(c0.y, bc[m], s0b);
            s1a = fmaf(c1.x, ba[m], s1a);
            s1b = fmaf(c1.y, bc[m], s1b);
        }
        const float2 u0 = ldcs2(up + 0 * HW2);
        const float2 u1 = ldcs2(up + 1 * HW2);
        const float2 r0 = ldcs2(rp + 0 * HW2);
        const float2 r1 = ldcs2(rp + 1 * HW2);
        y0a += u0.x * s0a + r0.x * sxa;
        y0b += u0.y * s0b + r0.y * sxb;
        y1a += u1.x * s1a + r1.x * sxa;
        y1b += u1.y * s1b + r1.y * sxb;

        cp += (size_t)(OUTC * COEFM) * HW2;
        up += (size_t)OUTC * HW2;
        rp += (size_t)OUTC * HW2;
    }

    float2* op = (float2*)(out + (size_t)b * OUTC * HW) + (size_t)(slice * 2) * HW2 + hw2;
    op[0 * HW2] = make_float2(y0a, y0b);
    op[1 * HW2] = make_float2(y1a, y1b);
}

extern "C" void kernel_launch(void* const* d_in, const int* in_sizes, int n_in,
                              void* d_out, int out_size)
{
    const float* x = (const float*)d_in[0];
    const float* w = (const float*)d_in[1];
    float* out = (float*)d_out;

    dim3 grid(16384 / TPB, OSPLIT);   // (128, 8) = 1024 blocks of 128 threads
    kan_kernel<<<grid, TPB>>>(x, w, out);
}